// round 2
// baseline (speedup 1.0000x reference)
#include <cuda_runtime.h>
#include <cuda_bf16.h>
#include <cstdint>

// ---------------------------------------------------------------------------
// GraphSAGE 3-layer: h = relu(mean_agg(x)@Wl + x@Wr + b), x3 (last no relu)
// Transform-then-aggregate: out = relu( scatter_mean(X@Wl) + X@Wr + b )
// Layer 2 scatters only 64 channels.
// ---------------------------------------------------------------------------

#define N_NODES 100000
#define N_EDGES 1600000

__device__ float g_yl[(size_t)N_NODES * 128];
__device__ float g_yr[(size_t)N_NODES * 128];
__device__ float g_bufA[(size_t)N_NODES * 128];
__device__ float g_bufB[(size_t)N_NODES * 128];
__device__ float g_deg[N_NODES];
__device__ int   g_is64;

// ---------------------------------------------------------------------------
// Detect edge_index element width. JAX defaults to x64-disabled, so the
// "int64" edge_index is almost certainly int32 — but decide from the data:
// int32 data viewed as int64 gives values >= 2^32 with prob ~1-1e-5/entry.
// ---------------------------------------------------------------------------
__global__ void detect_kernel(const void* ei) {
    const long long* e64 = (const long long*)ei;
    int is64 = 1;
    for (int i = 0; i < 64; i++) {
        long long v = e64[i];
        if (v < 0 || v >= N_NODES) { is64 = 0; break; }
    }
    g_is64 = is64;
}

__device__ __forceinline__ int load_idx(const void* ei, long long pos) {
    if (g_is64) return (int)((const long long*)ei)[pos];
    return ((const int*)ei)[pos];
}

// ---------------------------------------------------------------------------
__global__ void zero_kernel(float* __restrict__ p, int n4) {
    int i = blockIdx.x * blockDim.x + threadIdx.x;
    if (i < n4) reinterpret_cast<float4*>(p)[i] = make_float4(0.f, 0.f, 0.f, 0.f);
}

__global__ void deg_kernel(const void* __restrict__ ei, float* __restrict__ deg) {
    int e = blockIdx.x * blockDim.x + threadIdx.x;
    if (e < N_EDGES) {
        int d = load_idx(ei, (long long)N_EDGES + e);
        if ((unsigned)d < N_NODES) atomicAdd(&deg[d], 1.0f);
    }
}

// ---------------------------------------------------------------------------
// Streaming GEMM: Y[N, DOUT] = X[N, 128] @ W[128, DOUT]
// 64 rows x DOUT cols per 256-thread block; X tile in smem; W L1-resident.
// ---------------------------------------------------------------------------
template <int DOUT>
__global__ __launch_bounds__(256) void gemm128_kernel(
    const float* __restrict__ X, const float* __restrict__ W,
    float* __restrict__ Y)
{
    constexpr int TR = 64;
    __shared__ float sx[TR][132];

    const int row0 = blockIdx.x * TR;
    const int t = threadIdx.x;

    #pragma unroll
    for (int i = t; i < TR * 32; i += 256) {
        int r = i >> 5, c4 = i & 31;
        int gr = row0 + r;
        float4 v = make_float4(0.f, 0.f, 0.f, 0.f);
        if (gr < N_NODES)
            v = reinterpret_cast<const float4*>(X + (size_t)gr * 128)[c4];
        *reinterpret_cast<float4*>(&sx[r][c4 * 4]) = v;
    }
    __syncthreads();

    constexpr int CG  = DOUT / 4;      // col groups of 4
    constexpr int NG  = 256 / CG;      // row groups
    constexpr int RPT = TR / NG;       // rows per thread
    const int cg = t % CG;
    const int rg = t / CG;
    const int c0 = cg * 4;
    const int r0 = rg * RPT;

    float acc[RPT][4];
    #pragma unroll
    for (int r = 0; r < RPT; r++) {
        acc[r][0] = 0.f; acc[r][1] = 0.f; acc[r][2] = 0.f; acc[r][3] = 0.f;
    }

    const float4* __restrict__ W4 = reinterpret_cast<const float4*>(W + c0);

    #pragma unroll 4
    for (int k = 0; k < 128; k++) {
        float4 w = W4[k * CG];
        #pragma unroll
        for (int r = 0; r < RPT; r++) {
            float xv = sx[r0 + r][k];
            acc[r][0] += xv * w.x;
            acc[r][1] += xv * w.y;
            acc[r][2] += xv * w.z;
            acc[r][3] += xv * w.w;
        }
    }

    #pragma unroll
    for (int r = 0; r < RPT; r++) {
        int gr = row0 + r0 + r;
        if (gr < N_NODES) {
            float4 v = make_float4(acc[r][0], acc[r][1], acc[r][2], acc[r][3]);
            *reinterpret_cast<float4*>(Y + (size_t)gr * DOUT + c0) = v;
        }
    }
}

// ---------------------------------------------------------------------------
// Vectorized atomic scatter: agg[dst] += yl[src], DOUT channels per edge.
// DOUT/4 lanes cooperate per edge; red.global.add.v4.f32 (sm_90+).
// ---------------------------------------------------------------------------
template <int DOUT>
__global__ __launch_bounds__(256) void scatter_kernel(
    const float* __restrict__ yl, const void* __restrict__ ei,
    float* __restrict__ agg)
{
    constexpr int LPE = DOUT / 4;
    long long gid = (long long)blockIdx.x * blockDim.x + threadIdx.x;
    long long e = gid / LPE;
    int sub = (int)(gid % LPE);
    if (e >= N_EDGES) return;

    int s = load_idx(ei, e);
    int d = load_idx(ei, (long long)N_EDGES + e);
    if ((unsigned)s >= N_NODES || (unsigned)d >= N_NODES) return;

    float4 v = *reinterpret_cast<const float4*>(yl + (size_t)s * DOUT + sub * 4);
    float* p = agg + (size_t)d * DOUT + sub * 4;
    asm volatile("red.global.add.v4.f32 [%0], {%1,%2,%3,%4};"
                 :: "l"(p), "f"(v.x), "f"(v.y), "f"(v.z), "f"(v.w)
                 : "memory");
}

// ---------------------------------------------------------------------------
// Combine: out = maybe_relu(agg/max(deg,1) + yr + b)
// ---------------------------------------------------------------------------
template <int DOUT, bool RELU>
__global__ __launch_bounds__(256) void combine_kernel(
    const float* __restrict__ agg, const float* __restrict__ yr,
    const float* __restrict__ b, const float* __restrict__ deg,
    float* __restrict__ out)
{
    constexpr int C4 = DOUT / 4;
    int i = blockIdx.x * blockDim.x + threadIdx.x;
    if (i >= N_NODES * C4) return;
    int node = i / C4;
    int c4 = i % C4;

    float dinv = 1.0f / fmaxf(deg[node], 1.0f);
    float4 a = reinterpret_cast<const float4*>(agg)[i];
    float4 r = reinterpret_cast<const float4*>(yr)[i];
    float4 bb = reinterpret_cast<const float4*>(b)[c4];

    float4 o;
    o.x = a.x * dinv + r.x + bb.x;
    o.y = a.y * dinv + r.y + bb.y;
    o.z = a.z * dinv + r.z + bb.z;
    o.w = a.w * dinv + r.w + bb.w;
    if (RELU) {
        o.x = fmaxf(o.x, 0.f); o.y = fmaxf(o.y, 0.f);
        o.z = fmaxf(o.z, 0.f); o.w = fmaxf(o.w, 0.f);
    }
    reinterpret_cast<float4*>(out)[i] = o;
}

// ---------------------------------------------------------------------------
extern "C" void kernel_launch(void* const* d_in, const int* in_sizes, int n_in,
                              void* d_out, int out_size)
{
    const float* x   = (const float*)d_in[0];
    const void*  ei  = d_in[1];
    const float* Wl0 = (const float*)d_in[2];
    const float* Wr0 = (const float*)d_in[3];
    const float* b0  = (const float*)d_in[4];
    const float* Wl1 = (const float*)d_in[5];
    const float* Wr1 = (const float*)d_in[6];
    const float* b1  = (const float*)d_in[7];
    const float* Wl2 = (const float*)d_in[8];
    const float* Wr2 = (const float*)d_in[9];
    const float* b2  = (const float*)d_in[10];
    float* out = (float*)d_out;

    static float *p_yl = nullptr, *p_yr = nullptr, *p_A = nullptr, *p_B = nullptr, *p_deg = nullptr;
    if (!p_yl) {
        cudaGetSymbolAddress((void**)&p_yl,  g_yl);
        cudaGetSymbolAddress((void**)&p_yr,  g_yr);
        cudaGetSymbolAddress((void**)&p_A,   g_bufA);
        cudaGetSymbolAddress((void**)&p_B,   g_bufB);
        cudaGetSymbolAddress((void**)&p_deg, g_deg);
    }

    const int NB_GEMM   = (N_NODES + 63) / 64;
    const int N128_4    = N_NODES * 32;
    const int N64_4     = N_NODES * 16;
    const int SC128_BLK = (int)(((long long)N_EDGES * 32 + 255) / 256);
    const int SC64_BLK  = (int)(((long long)N_EDGES * 16 + 255) / 256);

    // --- dtype probe + degrees (recomputed every call: determinism) ---
    detect_kernel<<<1, 1>>>(ei);
    zero_kernel<<<(N_NODES / 4 + 255) / 256, 256>>>(p_deg, N_NODES / 4);
    deg_kernel<<<(N_EDGES + 255) / 256, 256>>>(ei, p_deg);

    // ---- Layer 0: x -> bufA (relu) ----
    gemm128_kernel<128><<<NB_GEMM, 256>>>(x, Wl0, p_yl);
    gemm128_kernel<128><<<NB_GEMM, 256>>>(x, Wr0, p_yr);
    zero_kernel<<<(N128_4 + 255) / 256, 256>>>(p_A, N128_4);
    scatter_kernel<128><<<SC128_BLK, 256>>>(p_yl, ei, p_A);
    combine_kernel<128, true><<<(N128_4 + 255) / 256, 256>>>(p_A, p_yr, b0, p_deg, p_A);

    // ---- Layer 1: bufA -> bufB (relu) ----
    gemm128_kernel<128><<<NB_GEMM, 256>>>(p_A, Wl1, p_yl);
    gemm128_kernel<128><<<NB_GEMM, 256>>>(p_A, Wr1, p_yr);
    zero_kernel<<<(N128_4 + 255) / 256, 256>>>(p_B, N128_4);
    scatter_kernel<128><<<SC128_BLK, 256>>>(p_yl, ei, p_B);
    combine_kernel<128, true><<<(N128_4 + 255) / 256, 256>>>(p_B, p_yr, b1, p_deg, p_B);

    // ---- Layer 2: bufB -> d_out (no relu, DOUT=64) ----
    gemm128_kernel<64><<<NB_GEMM, 256>>>(p_B, Wl2, p_yl);
    gemm128_kernel<64><<<NB_GEMM, 256>>>(p_B, Wr2, p_yr);
    zero_kernel<<<(N64_4 + 255) / 256, 256>>>(p_A, N64_4);
    scatter_kernel<64><<<SC64_BLK, 256>>>(p_yl, ei, p_A);
    combine_kernel<64, false><<<(N64_4 + 255) / 256, 256>>>(p_A, p_yr, b2, p_deg, out);
}

// round 4
// speedup vs baseline: 1.6362x; 1.6362x over previous
#include <cuda_runtime.h>
#include <cuda_bf16.h>
#include <cstdint>

// ---------------------------------------------------------------------------
// GraphSAGE 3-layer. Transform-then-aggregate + CSR gather with fused epilogue.
//   out = maybe_relu( csr_mean_gather(X@Wl) + X@Wr + b )
// ---------------------------------------------------------------------------

#define N_NODES 100000
#define N_EDGES 1600000

__device__ float g_yl[(size_t)N_NODES * 128];
__device__ float g_yr[(size_t)N_NODES * 128];
__device__ float g_bufA[(size_t)N_NODES * 128];
__device__ float g_bufB[(size_t)N_NODES * 128];
__device__ int   g_cnt[N_NODES];
__device__ int   g_off[N_NODES];
__device__ int   g_cur[N_NODES];
__device__ int   g_csr[N_EDGES];
__device__ int   g_bsum[128];
__device__ int   g_is64;

// --------------------------- edge dtype probe ------------------------------
__global__ void detect_kernel(const void* ei) {
    const long long* e64 = (const long long*)ei;
    int is64 = 1;
    for (int i = 0; i < 64; i++) {
        long long v = e64[i];
        if (v < 0 || v >= N_NODES) { is64 = 0; break; }
    }
    g_is64 = is64;
}

__device__ __forceinline__ int load_idx(const void* ei, long long pos) {
    if (g_is64) return (int)((const long long*)ei)[pos];
    return ((const int*)ei)[pos];
}

// ------------------------------- CSR build ---------------------------------
__global__ void zero_int_kernel(int* __restrict__ p, int n) {
    int i = blockIdx.x * blockDim.x + threadIdx.x;
    if (i < n) p[i] = 0;
}

__global__ void hist_kernel(const void* __restrict__ ei, int* __restrict__ cnt) {
    int e = blockIdx.x * blockDim.x + threadIdx.x;
    if (e < N_EDGES) {
        int d = load_idx(ei, (long long)N_EDGES + e);
        if ((unsigned)d < N_NODES) atomicAdd(&cnt[d], 1);
    }
}

// chunk = 1024 nodes per block
__global__ void blockreduce_kernel(const int* __restrict__ cnt, int* __restrict__ bsum) {
    __shared__ int sm[256];
    int b = blockIdx.x, t = threadIdx.x;
    int base = b * 1024 + t * 4;
    int s = 0;
    #pragma unroll
    for (int i = 0; i < 4; i++) {
        int idx = base + i;
        if (idx < N_NODES) s += cnt[idx];
    }
    sm[t] = s; __syncthreads();
    for (int st = 128; st > 0; st >>= 1) {
        if (t < st) sm[t] += sm[t + st];
        __syncthreads();
    }
    if (t == 0) bsum[b] = sm[0];
}

__global__ void scanpart_kernel(int* __restrict__ bsum, int nb) {
    if (threadIdx.x == 0) {
        int acc = 0;
        for (int i = 0; i < nb; i++) { int v = bsum[i]; bsum[i] = acc; acc += v; }
    }
}

__global__ void scanfinal_kernel(const int* __restrict__ cnt, const int* __restrict__ bsum,
                                 int* __restrict__ off, int* __restrict__ cur) {
    __shared__ int sm[256];
    int b = blockIdx.x, t = threadIdx.x;
    int base = b * 1024 + t * 4;
    int v[4]; int s = 0;
    #pragma unroll
    for (int i = 0; i < 4; i++) {
        int idx = base + i;
        v[i] = (idx < N_NODES) ? cnt[idx] : 0;
        s += v[i];
    }
    sm[t] = s; __syncthreads();
    for (int st = 1; st < 256; st <<= 1) {
        int x = (t >= st) ? sm[t - st] : 0;
        __syncthreads();
        sm[t] += x;
        __syncthreads();
    }
    int run = sm[t] - s + bsum[b];
    #pragma unroll
    for (int i = 0; i < 4; i++) {
        int idx = base + i;
        if (idx < N_NODES) { off[idx] = run; cur[idx] = run; }
        run += v[i];
    }
}

__global__ void fill_kernel(const void* __restrict__ ei, int* __restrict__ cur,
                            int* __restrict__ csr) {
    int e = blockIdx.x * blockDim.x + threadIdx.x;
    if (e < N_EDGES) {
        int s = load_idx(ei, e);
        int d = load_idx(ei, (long long)N_EDGES + e);
        if ((unsigned)s < N_NODES && (unsigned)d < N_NODES) {
            int p = atomicAdd(&cur[d], 1);
            csr[p] = s;
        }
    }
}

// ---------------------------------------------------------------------------
// Dual GEMM: Yl = X@Wl, Yr = X@Wr  (X: [N,128], W: [128,DOUT])
// 64 rows x DOUT cols per 256-thread block; shared X tile (float4-wide k),
// both outputs computed from one tile load.
// ---------------------------------------------------------------------------
__device__ __forceinline__ void fma4(float4& acc, float s, const float4& wv) {
    acc.x += s * wv.x; acc.y += s * wv.y;
    acc.z += s * wv.z; acc.w += s * wv.w;
}

template <int DOUT>
__global__ __launch_bounds__(256) void gemm_dual_kernel(
    const float* __restrict__ X,
    const float* __restrict__ Wl, const float* __restrict__ Wr,
    float* __restrict__ Yl, float* __restrict__ Yr)
{
    constexpr int TR = 64;
    __shared__ float4 sx[TR][33];   // padded row stride

    const int row0 = blockIdx.x * TR;
    const int t = threadIdx.x;

    #pragma unroll
    for (int i = t; i < TR * 32; i += 256) {
        int r = i >> 5, c4 = i & 31;
        int gr = row0 + r;
        float4 v = make_float4(0.f, 0.f, 0.f, 0.f);
        if (gr < N_NODES)
            v = reinterpret_cast<const float4*>(X + (size_t)gr * 128)[c4];
        sx[r][c4] = v;
    }
    __syncthreads();

    constexpr int CG  = DOUT / 4;
    constexpr int NG  = 256 / CG;
    constexpr int RPT = TR / NG;      // 8 for DOUT=128, 4 for DOUT=64
    const int cg = t % CG;
    const int rg = t / CG;
    const int c0 = cg * 4;
    const int r0 = rg * RPT;

    float4 accl[RPT], accr[RPT];
    #pragma unroll
    for (int r = 0; r < RPT; r++) {
        accl[r] = make_float4(0.f, 0.f, 0.f, 0.f);
        accr[r] = make_float4(0.f, 0.f, 0.f, 0.f);
    }

    const float4* __restrict__ Wl4 = reinterpret_cast<const float4*>(Wl + c0);
    const float4* __restrict__ Wr4 = reinterpret_cast<const float4*>(Wr + c0);

    #pragma unroll 2
    for (int kq = 0; kq < 32; kq++) {
        const int k0 = kq * 4;
        float4 wl0 = Wl4[(k0 + 0) * CG];
        float4 wl1 = Wl4[(k0 + 1) * CG];
        float4 wl2 = Wl4[(k0 + 2) * CG];
        float4 wl3 = Wl4[(k0 + 3) * CG];
        float4 wr0 = Wr4[(k0 + 0) * CG];
        float4 wr1 = Wr4[(k0 + 1) * CG];
        float4 wr2 = Wr4[(k0 + 2) * CG];
        float4 wr3 = Wr4[(k0 + 3) * CG];
        #pragma unroll
        for (int r = 0; r < RPT; r++) {
            float4 xv = sx[r0 + r][kq];
            fma4(accl[r], xv.x, wl0); fma4(accl[r], xv.y, wl1);
            fma4(accl[r], xv.z, wl2); fma4(accl[r], xv.w, wl3);
            fma4(accr[r], xv.x, wr0); fma4(accr[r], xv.y, wr1);
            fma4(accr[r], xv.z, wr2); fma4(accr[r], xv.w, wr3);
        }
    }

    #pragma unroll
    for (int r = 0; r < RPT; r++) {
        int gr = row0 + r0 + r;
        if (gr < N_NODES) {
            *reinterpret_cast<float4*>(Yl + (size_t)gr * DOUT + c0) = accl[r];
            *reinterpret_cast<float4*>(Yr + (size_t)gr * DOUT + c0) = accr[r];
        }
    }
}

// ---------------------------------------------------------------------------
// Fused gather + epilogue (128 ch): one warp per dst node.
// out[n] = maybe_relu( (sum_{s in N(n)} yl[s]) / max(deg,1) + yr[n] + b )
// ---------------------------------------------------------------------------
template <bool RELU>
__global__ __launch_bounds__(256) void gather128_kernel(
    const float* __restrict__ yl, const float* __restrict__ yr,
    const float* __restrict__ b,
    const int* __restrict__ csr, const int* __restrict__ off,
    const int* __restrict__ cnt, float* __restrict__ out)
{
    int warp = (blockIdx.x * 256 + threadIdx.x) >> 5;
    int lane = threadIdx.x & 31;
    if (warp >= N_NODES) return;

    const int c = cnt[warp];
    const int o = off[warp];
    const float4* __restrict__ yl4 = reinterpret_cast<const float4*>(yl);

    float4 acc = make_float4(0.f, 0.f, 0.f, 0.f);
    int j = 0;
    for (; j + 4 <= c; j += 4) {
        int s0 = csr[o + j + 0];
        int s1 = csr[o + j + 1];
        int s2 = csr[o + j + 2];
        int s3 = csr[o + j + 3];
        float4 a0 = yl4[(size_t)s0 * 32 + lane];
        float4 a1 = yl4[(size_t)s1 * 32 + lane];
        float4 a2 = yl4[(size_t)s2 * 32 + lane];
        float4 a3 = yl4[(size_t)s3 * 32 + lane];
        acc.x += a0.x + a1.x + a2.x + a3.x;
        acc.y += a0.y + a1.y + a2.y + a3.y;
        acc.z += a0.z + a1.z + a2.z + a3.z;
        acc.w += a0.w + a1.w + a2.w + a3.w;
    }
    for (; j < c; j++) {
        int s = csr[o + j];
        float4 a = yl4[(size_t)s * 32 + lane];
        acc.x += a.x; acc.y += a.y; acc.z += a.z; acc.w += a.w;
    }

    float dinv = 1.0f / fmaxf((float)c, 1.0f);
    float4 r  = reinterpret_cast<const float4*>(yr)[(size_t)warp * 32 + lane];
    float4 bb = reinterpret_cast<const float4*>(b)[lane];
    float4 o4;
    o4.x = acc.x * dinv + r.x + bb.x;
    o4.y = acc.y * dinv + r.y + bb.y;
    o4.z = acc.z * dinv + r.z + bb.z;
    o4.w = acc.w * dinv + r.w + bb.w;
    if (RELU) {
        o4.x = fmaxf(o4.x, 0.f); o4.y = fmaxf(o4.y, 0.f);
        o4.z = fmaxf(o4.z, 0.f); o4.w = fmaxf(o4.w, 0.f);
    }
    reinterpret_cast<float4*>(out)[(size_t)warp * 32 + lane] = o4;
}

// 64-channel variant: one half-warp per node.
template <bool RELU>
__global__ __launch_bounds__(256) void gather64_kernel(
    const float* __restrict__ yl, const float* __restrict__ yr,
    const float* __restrict__ b,
    const int* __restrict__ csr, const int* __restrict__ off,
    const int* __restrict__ cnt, float* __restrict__ out)
{
    int node = (blockIdx.x * 256 + threadIdx.x) >> 4;
    int sub  = threadIdx.x & 15;
    if (node >= N_NODES) return;

    const int c = cnt[node];
    const int o = off[node];
    const float4* __restrict__ yl4 = reinterpret_cast<const float4*>(yl);

    float4 acc = make_float4(0.f, 0.f, 0.f, 0.f);
    int j = 0;
    for (; j + 4 <= c; j += 4) {
        int s0 = csr[o + j + 0];
        int s1 = csr[o + j + 1];
        int s2 = csr[o + j + 2];
        int s3 = csr[o + j + 3];
        float4 a0 = yl4[(size_t)s0 * 16 + sub];
        float4 a1 = yl4[(size_t)s1 * 16 + sub];
        float4 a2 = yl4[(size_t)s2 * 16 + sub];
        float4 a3 = yl4[(size_t)s3 * 16 + sub];
        acc.x += a0.x + a1.x + a2.x + a3.x;
        acc.y += a0.y + a1.y + a2.y + a3.y;
        acc.z += a0.z + a1.z + a2.z + a3.z;
        acc.w += a0.w + a1.w + a2.w + a3.w;
    }
    for (; j < c; j++) {
        int s = csr[o + j];
        float4 a = yl4[(size_t)s * 16 + sub];
        acc.x += a.x; acc.y += a.y; acc.z += a.z; acc.w += a.w;
    }

    float dinv = 1.0f / fmaxf((float)c, 1.0f);
    float4 r  = reinterpret_cast<const float4*>(yr)[(size_t)node * 16 + sub];
    float4 bb = reinterpret_cast<const float4*>(b)[sub];
    float4 o4;
    o4.x = acc.x * dinv + r.x + bb.x;
    o4.y = acc.y * dinv + r.y + bb.y;
    o4.z = acc.z * dinv + r.z + bb.z;
    o4.w = acc.w * dinv + r.w + bb.w;
    if (RELU) {
        o4.x = fmaxf(o4.x, 0.f); o4.y = fmaxf(o4.y, 0.f);
        o4.z = fmaxf(o4.z, 0.f); o4.w = fmaxf(o4.w, 0.f);
    }
    reinterpret_cast<float4*>(out)[(size_t)node * 16 + sub] = o4;
}

// ---------------------------------------------------------------------------
extern "C" void kernel_launch(void* const* d_in, const int* in_sizes, int n_in,
                              void* d_out, int out_size)
{
    const float* x   = (const float*)d_in[0];
    const void*  ei  = d_in[1];
    const float* Wl0 = (const float*)d_in[2];
    const float* Wr0 = (const float*)d_in[3];
    const float* b0  = (const float*)d_in[4];
    const float* Wl1 = (const float*)d_in[5];
    const float* Wr1 = (const float*)d_in[6];
    const float* b1  = (const float*)d_in[7];
    const float* Wl2 = (const float*)d_in[8];
    const float* Wr2 = (const float*)d_in[9];
    const float* b2  = (const float*)d_in[10];
    float* out = (float*)d_out;

    static float *p_yl = nullptr, *p_yr = nullptr, *p_A = nullptr, *p_B = nullptr;
    static int *p_cnt = nullptr, *p_off = nullptr, *p_cur = nullptr, *p_csr = nullptr, *p_bsum = nullptr;
    if (!p_yl) {
        cudaGetSymbolAddress((void**)&p_yl,   g_yl);
        cudaGetSymbolAddress((void**)&p_yr,   g_yr);
        cudaGetSymbolAddress((void**)&p_A,    g_bufA);
        cudaGetSymbolAddress((void**)&p_B,    g_bufB);
        cudaGetSymbolAddress((void**)&p_cnt,  g_cnt);
        cudaGetSymbolAddress((void**)&p_off,  g_off);
        cudaGetSymbolAddress((void**)&p_cur,  g_cur);
        cudaGetSymbolAddress((void**)&p_csr,  g_csr);
        cudaGetSymbolAddress((void**)&p_bsum, g_bsum);
    }

    const int NB_GEMM  = (N_NODES + 63) / 64;
    const int NB_SCAN  = (N_NODES + 1023) / 1024;        // 98
    const int NB_EDGE  = (N_EDGES + 255) / 256;
    const int NB_G128  = (N_NODES * 32 + 255) / 256;     // warp per node
    const int NB_G64   = (N_NODES * 16 + 255) / 256;     // half-warp per node

    // --- CSR build (recomputed every call: determinism) ---
    detect_kernel<<<1, 1>>>(ei);
    zero_int_kernel<<<(N_NODES + 255) / 256, 256>>>(p_cnt, N_NODES);
    hist_kernel<<<NB_EDGE, 256>>>(ei, p_cnt);
    blockreduce_kernel<<<NB_SCAN, 256>>>(p_cnt, p_bsum);
    scanpart_kernel<<<1, 32>>>(p_bsum, NB_SCAN);
    scanfinal_kernel<<<NB_SCAN, 256>>>(p_cnt, p_bsum, p_off, p_cur);
    fill_kernel<<<NB_EDGE, 256>>>(ei, p_cur, p_csr);

    // ---- Layer 0: x -> bufA (relu) ----
    gemm_dual_kernel<128><<<NB_GEMM, 256>>>(x, Wl0, Wr0, p_yl, p_yr);
    gather128_kernel<true><<<NB_G128, 256>>>(p_yl, p_yr, b0, p_csr, p_off, p_cnt, p_A);

    // ---- Layer 1: bufA -> bufB (relu) ----
    gemm_dual_kernel<128><<<NB_GEMM, 256>>>(p_A, Wl1, Wr1, p_yl, p_yr);
    gather128_kernel<true><<<NB_G128, 256>>>(p_yl, p_yr, b1, p_csr, p_off, p_cnt, p_B);

    // ---- Layer 2: bufB -> d_out (no relu, 64 ch) ----
    gemm_dual_kernel<64><<<NB_GEMM, 256>>>(p_B, Wl2, Wr2, p_yl, p_yr);
    gather64_kernel<false><<<NB_G64, 256>>>(p_yl, p_yr, b2, p_csr, p_off, p_cnt, out);
}